// round 8
// baseline (speedup 1.0000x reference)
#include <cuda_runtime.h>

#define NB   2
#define NP   8192
#define KNN  10
#define K1   11
#define WPB  8
#define BLK  (WPB * 32)
#define NQ   (NB * NP)          // 16384
#define NBLK (NQ / WPB)         // 2048
#define FULL 0xFFFFFFFFu

#define G     64                // grid is G x G per batch (2D bins over x,y)
#define GC    (G * G)           // 4096 cells/batch
#define NCELL (NB * GC)         // 8192
#define H     0.25f
#define INVH  4.0f
#define X0    (-8.0f)

// Scratch (no allocations allowed).
__device__ float4 g_ptsa[NQ];       // packed (x,y,z,|p|^2), original order
__device__ int    g_cellid[NQ];
__device__ int    g_cnt[NCELL];
__device__ int    g_off[NCELL + 1];
__device__ int    g_cur[NCELL];
__device__ float4 g_sorted[NQ];     // cell-sorted points
__device__ int    g_sidx[NQ];       // within-batch original index
__device__ float  g_part[NBLK];

// ---------------------------------------------------------------------------
__global__ void zero_cnt_kernel() {
    int i = blockIdx.x * blockDim.x + threadIdx.x;
    if (i < NCELL) g_cnt[i] = 0;
}

__device__ __forceinline__ int cell_coord(float v) {
    int c = (int)floorf((v - X0) * INVH);
    return min(max(c, 0), G - 1);
}

__global__ void bin_count_kernel(const float* __restrict__ p1) {
    int i = blockIdx.x * blockDim.x + threadIdx.x;
    if (i < NQ) {
        float x = p1[3 * i + 0];
        float y = p1[3 * i + 1];
        float z = p1[3 * i + 2];
        g_ptsa[i] = make_float4(x, y, z, x * x + y * y + z * z);
        int c = (i >> 13) * GC + cell_coord(y) * G + cell_coord(x);
        g_cellid[i] = c;
        atomicAdd(&g_cnt[c], 1);
    }
}

// Single-block exclusive scan over NCELL counts (8 cells per thread).
__global__ void scan_kernel() {
    __shared__ int sp[1024];
    const int t = threadIdx.x;
    const int base = t * (NCELL / 1024);   // 8
    int loc[NCELL / 1024];
    int s = 0;
#pragma unroll
    for (int k = 0; k < NCELL / 1024; ++k) { loc[k] = g_cnt[base + k]; s += loc[k]; }
    sp[t] = s;
    __syncthreads();
    for (int off = 1; off < 1024; off <<= 1) {
        int v = (t >= off) ? sp[t - off] : 0;
        __syncthreads();
        sp[t] += v;
        __syncthreads();
    }
    int run = sp[t] - s;   // exclusive prefix of this thread's chunk
#pragma unroll
    for (int k = 0; k < NCELL / 1024; ++k) {
        g_off[base + k] = run;
        g_cur[base + k] = run;
        run += loc[k];
    }
    if (t == 1023) g_off[NCELL] = sp[1023];
}

__global__ void scatter_kernel() {
    int i = blockIdx.x * blockDim.x + threadIdx.x;
    if (i < NQ) {
        int pos = atomicAdd(&g_cur[g_cellid[i]], 1);
        g_sorted[pos] = g_ptsa[i];
        g_sidx[pos] = i & (NP - 1);
    }
}

// ---------------------------------------------------------------------------
// ONE QUERY PER WARP with lane-distributed top-11 (lane t holds t-th smallest
// (key, sorted_pos)); keys are uint bit-images of clamped nonneg d2. Grid ring
// search with exact termination: after processing all cells of Chebyshev
// index-radius <= r, any unseen point is >= r*H away, so stop when the 11th
// key <= (r*H)^2. Unconverged tail queries do a fresh brute rescan.
// ---------------------------------------------------------------------------
__global__ void __launch_bounds__(BLK) knn_loss_kernel(const float* __restrict__ p2) {
    const int w    = threadIdx.x >> 5;
    const int lane = threadIdx.x & 31;
    const int q    = blockIdx.x * WPB + w;
    const int b    = q >> 13;
    const int qi   = q & (NP - 1);

    const float4 me = g_ptsa[q];
    const float cx = -2.0f * me.x;
    const float cy = -2.0f * me.y;
    const float cz = -2.0f * me.z;
    const float base = me.w;

    const int qcx = cell_coord(me.x);
    const int qcy = cell_coord(me.y);
    const int cb  = b * GC;

    unsigned ekey = FULL;   // distributed list entry (lanes 0..10)
    int      eidx = 0;      // sorted position of entry
    unsigned dkmax = FULL;  // 11th-smallest key (lane 10's entry)

    auto slab = [&](unsigned key, int j) {
        unsigned wm = __reduce_min_sync(FULL, key);
        if (wm >= dkmax) return;
        while (true) {
            unsigned wk = __reduce_min_sync(FULL, key);
            if (wk >= dkmax) break;                      // uniform exit
            unsigned bal = __ballot_sync(FULL, key == wk);
            int src = __ffs(bal) - 1;
            int ji  = __shfl_sync(FULL, j, src);
            unsigned keep = __ballot_sync(FULL, ekey <= wk);
            int pos = __popc(keep & 0x7FFu);
            unsigned pk = __shfl_up_sync(FULL, ekey, 1);
            int      pi = __shfl_up_sync(FULL, eidx, 1);
            bool take  = (lane == pos);
            bool shift = (lane > pos) && (lane <= 10);
            ekey = take ? wk : (shift ? pk : ekey);
            eidx = take ? ji : (shift ? pi : eidx);
            dkmax = __shfl_sync(FULL, ekey, 10);
            if (lane == src) key = FULL;
        }
    };

    auto do_cell = [&](int cell) {
        int s = __ldg(&g_off[cell]);
        int e = __ldg(&g_off[cell + 1]);
        for (int t0 = s; t0 < e; t0 += 32) {
            int j = t0 + lane;
            unsigned key = FULL;
            if (j < e) {
                float4 p = __ldg(&g_sorted[j]);
                float d = fmaf(p.x, cx, fmaf(p.y, cy, fmaf(p.z, cz, base + p.w)));
                key = __float_as_uint(fmaxf(d, 0.0f));
            }
            slab(key, j);
        }
    };

    // Rings 0..1: center cell first (saturates dkmax early), then 3x3 rest.
    do_cell(cb + qcy * G + qcx);
    for (int dy = -1; dy <= 1; ++dy) {
        int yy = qcy + dy;
        if (yy < 0 || yy >= G) continue;
        for (int dx = -1; dx <= 1; ++dx) {
            int xx = qcx + dx;
            if (xx < 0 || xx >= G) continue;
            if (dx == 0 && dy == 0) continue;
            do_cell(cb + yy * G + xx);
        }
    }
    bool done = (dkmax <= __float_as_uint(H * H));

    for (int r = 2; r <= 4 && !done; ++r) {
        int ylo = qcy - r, yhi = qcy + r;
        int xlo = qcx - r, xhi = qcx + r;
        for (int xx = xlo; xx <= xhi; ++xx) {
            if (xx < 0 || xx >= G) continue;
            if (ylo >= 0) do_cell(cb + ylo * G + xx);
            if (yhi < G)  do_cell(cb + yhi * G + xx);
        }
        for (int yy = ylo + 1; yy <= yhi - 1; ++yy) {
            if (yy < 0 || yy >= G) continue;
            if (xlo >= 0) do_cell(cb + yy * G + xlo);
            if (xhi < G)  do_cell(cb + yy * G + xhi);
        }
        float bd = (r * H) * (r * H);
        done = (dkmax <= __float_as_uint(bd));
    }

    if (!done) {  // deep-tail fallback: fresh exact brute scan of this batch
        ekey = FULL; eidx = 0; dkmax = FULL;
        const int s0 = b * NP;
        for (int t0 = 0; t0 < NP; t0 += 32) {
            int j = s0 + t0 + lane;
            float4 p = __ldg(&g_sorted[j]);
            float d = fmaf(p.x, cx, fmaf(p.y, cy, fmaf(p.z, cz, base + p.w)));
            slab(__float_as_uint(fmaxf(d, 0.0f)), j);
        }
    }

    // Lane 0 holds self (key 0, strict min) -> dropped; lanes 1..10 gather.
    float sx = 0.f, sy = 0.f, sz = 0.f;
    float rx = 0.f, ry = 0.f, rz = 0.f;
    if (lane >= 1 && lane < K1) {
        float4 pn = __ldg(&g_sorted[eidx]);
        sx = pn.x; sy = pn.y; sz = pn.z;
        int orig = __ldg(&g_sidx[eidx]);
        const float* r2 = p2 + (size_t)(b * NP + orig) * 3;
        rx = __ldg(r2 + 0); ry = __ldg(r2 + 1); rz = __ldg(r2 + 2);
    }
#pragma unroll
    for (int off = 8; off > 0; off >>= 1) {
        sx += __shfl_down_sync(FULL, sx, off, 16);
        sy += __shfl_down_sync(FULL, sy, off, 16);
        sz += __shfl_down_sync(FULL, sz, off, 16);
        rx += __shfl_down_sync(FULL, rx, off, 16);
        ry += __shfl_down_sync(FULL, ry, off, 16);
        rz += __shfl_down_sync(FULL, rz, off, 16);
    }

    __shared__ float sred[WPB];
    if (lane == 0) {
        const float* mq2 = p2 + (size_t)(b * NP + qi) * 3;
        const float inv = 1.0f / (float)KNN;
        float v = fabsf((sx * inv - me.x) - (rx * inv - mq2[0]))
                + fabsf((sy * inv - me.y) - (ry * inv - mq2[1]))
                + fabsf((sz * inv - me.z) - (rz * inv - mq2[2]));
        sred[w] = v;
    }
    __syncthreads();
    if (threadIdx.x == 0) {
        float s = 0.0f;
#pragma unroll
        for (int i = 0; i < WPB; ++i) s += sred[i];
        g_part[blockIdx.x] = s;
    }
}

// ---------------------------------------------------------------------------
__global__ void reduce_kernel(float* __restrict__ out) {
    __shared__ float red[256];
    float s = 0.0f;
    for (int i = threadIdx.x; i < NBLK; i += 256) s += g_part[i];
    red[threadIdx.x] = s;
    __syncthreads();
    for (int st = 128; st > 0; st >>= 1) {
        if (threadIdx.x < st) red[threadIdx.x] += red[threadIdx.x + st];
        __syncthreads();
    }
    if (threadIdx.x == 0) out[0] = red[0] / (float)(NB * NP * 3);
}

extern "C" void kernel_launch(void* const* d_in, const int* in_sizes, int n_in,
                              void* d_out, int out_size) {
    const float* p1 = (const float*)d_in[0];
    const float* p2 = (const float*)d_in[1];
    float* out = (float*)d_out;

    zero_cnt_kernel<<<(NCELL + 255) / 256, 256>>>();
    bin_count_kernel<<<(NQ + 255) / 256, 256>>>(p1);
    scan_kernel<<<1, 1024>>>();
    scatter_kernel<<<(NQ + 255) / 256, 256>>>();
    knn_loss_kernel<<<NBLK, BLK>>>(p2);
    reduce_kernel<<<1, 256>>>(out);
}

// round 17
// speedup vs baseline: 1.1054x; 1.1054x over previous
#include <cuda_runtime.h>

#define NB   2
#define NP   8192
#define KNN  10
#define K1   11
#define WPB  8
#define BLK  (WPB * 32)
#define NQ   (NB * NP)          // 16384
#define NBLK (NQ / WPB)         // 2048
#define FULL 0xFFFFFFFFu

#define NBIN  1024              // x-bins per batch
#define NBT   (NB * NBIN)       // 2048 total
#define X0    (-8.0f)
#define DELTA (16.0f / NBIN)    // 0.015625
#define INVD  (NBIN / 16.0f)    // 64

// Scratch (no allocations allowed).
__device__ float4 g_ptsa[NQ];      // packed (x,y,z,|p|^2), original order
__device__ int    g_bin[NQ];
__device__ int    g_cnt[NBT];
__device__ int    g_off[NBT + 1];
__device__ int    g_cur[NBT];
__device__ float4 g_sorted[NQ];    // x-bin-sorted points
__device__ int    g_sidx[NQ];      // within-batch original index
__device__ float  g_part[NBLK];

// ---------------------------------------------------------------------------
__global__ void zero_cnt_kernel() {
    int i = blockIdx.x * blockDim.x + threadIdx.x;
    if (i < NBT) g_cnt[i] = 0;
}

__device__ __forceinline__ int xbin(float x) {
    int c = (int)floorf((x - X0) * INVD);
    return min(max(c, 0), NBIN - 1);
}

__global__ void bin_count_kernel(const float* __restrict__ p1) {
    int i = blockIdx.x * blockDim.x + threadIdx.x;
    if (i < NQ) {
        float x = p1[3 * i + 0];
        float y = p1[3 * i + 1];
        float z = p1[3 * i + 2];
        g_ptsa[i] = make_float4(x, y, z, x * x + y * y + z * z);
        int c = (i >> 13) * NBIN + xbin(x);
        g_bin[i] = c;
        atomicAdd(&g_cnt[c], 1);
    }
}

// Single-block exclusive scan over NBT counts (2 bins per thread).
__global__ void scan_kernel() {
    __shared__ int sp[1024];
    const int t = threadIdx.x;
    const int base = t * 2;
    int l0 = g_cnt[base], l1 = g_cnt[base + 1];
    int s = l0 + l1;
    sp[t] = s;
    __syncthreads();
    for (int off = 1; off < 1024; off <<= 1) {
        int v = (t >= off) ? sp[t - off] : 0;
        __syncthreads();
        sp[t] += v;
        __syncthreads();
    }
    int run = sp[t] - s;
    g_off[base] = run;     g_cur[base] = run;
    g_off[base + 1] = run + l0; g_cur[base + 1] = run + l0;
    if (t == 1023) g_off[NBT] = sp[1023];
}

__global__ void scatter_kernel() {
    int i = blockIdx.x * blockDim.x + threadIdx.x;
    if (i < NQ) {
        int pos = atomicAdd(&g_cur[g_bin[i]], 1);
        g_sorted[pos] = g_ptsa[i];
        g_sidx[pos] = i & (NP - 1);
    }
}

// ---------------------------------------------------------------------------
// ONE QUERY PER WARP; lane-distributed top-11 (lane t = t-th smallest
// (key, sorted_pos)), keys = uint bits of clamped nonneg d2. The candidate
// window is a CONTIGUOUS range of the x-sorted array, expanded bin-by-bin
// toward the smaller x-gap. Exact termination: unseen-left x < X0+binlo*d,
// unseen-right x >= X0+(binhi+1)*d, so stop when mingap^2 >= dkmax.
// ---------------------------------------------------------------------------
__global__ void __launch_bounds__(BLK) knn_loss_kernel(const float* __restrict__ p2) {
    const int w    = threadIdx.x >> 5;
    const int lane = threadIdx.x & 31;
    const int q    = blockIdx.x * WPB + w;
    const int b    = q >> 13;
    const int qi   = q & (NP - 1);

    const float4 me = g_ptsa[q];
    const float cx = -2.0f * me.x;
    const float cy = -2.0f * me.y;
    const float cz = -2.0f * me.z;
    const float base = me.w;

    unsigned ekey = FULL;   // distributed list entry (lanes 0..10)
    int      eidx = 0;      // sorted position of entry
    unsigned dkmax = FULL;  // 11th-smallest key (lane 10's entry)

    auto slab = [&](unsigned key, int j) {
        unsigned wm = __reduce_min_sync(FULL, key);
        if (wm >= dkmax) return;
        while (true) {
            unsigned wk = __reduce_min_sync(FULL, key);
            if (wk >= dkmax) break;                      // uniform exit
            unsigned bal = __ballot_sync(FULL, key == wk);
            int src = __ffs(bal) - 1;
            int ji  = __shfl_sync(FULL, j, src);
            unsigned keep = __ballot_sync(FULL, ekey <= wk);
            int pos = __popc(keep & 0x7FFu);
            unsigned pk = __shfl_up_sync(FULL, ekey, 1);
            int      pi = __shfl_up_sync(FULL, eidx, 1);
            bool take  = (lane == pos);
            bool shift = (lane > pos) && (lane <= 10);
            ekey = take ? wk : (shift ? pk : ekey);
            eidx = take ? ji : (shift ? pi : eidx);
            dkmax = __shfl_sync(FULL, ekey, 10);
            if (lane == src) key = FULL;
        }
    };

    auto do_range = [&](int s, int e) {
        for (int t0 = s; t0 < e; t0 += 32) {
            int j = t0 + lane;
            unsigned key = FULL;
            if (j < e) {
                float4 p = __ldg(&g_sorted[j]);
                float d = fmaf(p.x, cx, fmaf(p.y, cy, fmaf(p.z, cz, base + p.w)));
                key = __float_as_uint(fmaxf(d, 0.0f));
            }
            slab(key, j);
        }
    };

    const int ob = b * NBIN;
    const int qb = xbin(me.x);
    int binlo = qb, binhi = qb;
    do_range(__ldg(&g_off[ob + qb]), __ldg(&g_off[ob + qb + 1]));

    for (int iter = 0; iter < NBIN; ++iter) {
        float dl = (binlo > 0)        ? fmaxf(me.x - (X0 + binlo * DELTA), 0.0f) : 3.0e38f;
        float dr = (binhi < NBIN - 1) ? fmaxf((X0 + (binhi + 1) * DELTA) - me.x, 0.0f) : 3.0e38f;
        float gap = fminf(dl, dr);
        if (gap > 1.0e30f) break;                            // both sides exhausted
        if (__float_as_uint(gap * gap) >= dkmax) break;      // exact termination
        int nb;
        if (dl <= dr) { --binlo; nb = binlo; } else { ++binhi; nb = binhi; }
        do_range(__ldg(&g_off[ob + nb]), __ldg(&g_off[ob + nb + 1]));
    }

    // Lane 0 holds self (key 0, strict min) -> dropped; lanes 1..10 gather.
    float sx = 0.f, sy = 0.f, sz = 0.f;
    float rx = 0.f, ry = 0.f, rz = 0.f;
    if (lane >= 1 && lane < K1) {
        float4 pn = __ldg(&g_sorted[eidx]);
        sx = pn.x; sy = pn.y; sz = pn.z;
        int orig = __ldg(&g_sidx[eidx]);
        const float* r2 = p2 + (size_t)(b * NP + orig) * 3;
        rx = __ldg(r2 + 0); ry = __ldg(r2 + 1); rz = __ldg(r2 + 2);
    }
#pragma unroll
    for (int off = 8; off > 0; off >>= 1) {
        sx += __shfl_down_sync(FULL, sx, off, 16);
        sy += __shfl_down_sync(FULL, sy, off, 16);
        sz += __shfl_down_sync(FULL, sz, off, 16);
        rx += __shfl_down_sync(FULL, rx, off, 16);
        ry += __shfl_down_sync(FULL, ry, off, 16);
        rz += __shfl_down_sync(FULL, rz, off, 16);
    }

    __shared__ float sred[WPB];
    if (lane == 0) {
        const float* mq2 = p2 + (size_t)(b * NP + qi) * 3;
        const float inv = 1.0f / (float)KNN;
        float v = fabsf((sx * inv - me.x) - (rx * inv - mq2[0]))
                + fabsf((sy * inv - me.y) - (ry * inv - mq2[1]))
                + fabsf((sz * inv - me.z) - (rz * inv - mq2[2]));
        sred[w] = v;
    }
    __syncthreads();
    if (threadIdx.x == 0) {
        float s = 0.0f;
#pragma unroll
        for (int i = 0; i < WPB; ++i) s += sred[i];
        g_part[blockIdx.x] = s;
    }
}

// ---------------------------------------------------------------------------
__global__ void reduce_kernel(float* __restrict__ out) {
    __shared__ float red[256];
    float s = 0.0f;
    for (int i = threadIdx.x; i < NBLK; i += 256) s += g_part[i];
    red[threadIdx.x] = s;
    __syncthreads();
    for (int st = 128; st > 0; st >>= 1) {
        if (threadIdx.x < st) red[threadIdx.x] += red[threadIdx.x + st];
        __syncthreads();
    }
    if (threadIdx.x == 0) out[0] = red[0] / (float)(NB * NP * 3);
}

extern "C" void kernel_launch(void* const* d_in, const int* in_sizes, int n_in,
                              void* d_out, int out_size) {
    const float* p1 = (const float*)d_in[0];
    const float* p2 = (const float*)d_in[1];
    float* out = (float*)d_out;

    zero_cnt_kernel<<<(NBT + 255) / 256, 256>>>();
    bin_count_kernel<<<(NQ + 255) / 256, 256>>>(p1);
    scan_kernel<<<1, 1024>>>();
    scatter_kernel<<<(NQ + 255) / 256, 256>>>();
    knn_loss_kernel<<<NBLK, BLK>>>(p2);
    reduce_kernel<<<1, 256>>>(out);
}